// round 7
// baseline (speedup 1.0000x reference)
#include <cuda_runtime.h>
#include <math.h>

#define LDIM 96           // L
#define FDIM 192          // 2L
#define TILE_R 64         // rows per tile
#define NTHREADS 512
#define PAD 65            // odd pad -> conflict-free strided smem access

// Folded DCT * W1 matrix (96 x 192), recomputed every launch (deterministic).
__device__ float g_M1[LDIM * FDIM];

// M1[n][j] = sum_f 2*cos(pi*(2n+1)*f/(2*96)) * W1[f][j], fp64 accumulation.
__global__ void precompute_m1_kernel(const float* __restrict__ W1) {
    int n = blockIdx.x;    // 0..95
    int j = threadIdx.x;   // 0..191
    double base = 3.14159265358979323846 * (2.0 * (double)n + 1.0) / (2.0 * (double)LDIM);
    double acc = 0.0;
    for (int f = 0; f < LDIM; ++f) {
        acc += 2.0 * cos(base * (double)f) * (double)W1[f * FDIM + j];
    }
    g_M1[n * FDIM + j] = (float)acc;
}

__global__ void __launch_bounds__(NTHREADS, 1)
fused_dct_mlp_ln_kernel(const float* __restrict__ x,
                        const float* __restrict__ W2,
                        const float* __restrict__ gamma,
                        const float* __restrict__ beta,
                        float* __restrict__ out,
                        int ntiles)
{
    extern __shared__ float smv[];
    float* M1s = smv;                          // [96][192]   73,728 B
    float* W2s = M1s + LDIM * FDIM;            // [192][96]   73,728 B
    float* Xs  = W2s + FDIM * LDIM;            // [96][PAD]   24,960 B  (k-major, transposed)
    float* Hs  = Xs + LDIM * PAD;              // [192][PAD]  49,920 B  (k-major, transposed)

    const int tid  = threadIdx.x;
    const int lane = tid & 31;
    const int wid  = tid >> 5;        // 0..15; each warp owns 4 rows
    const int r0   = wid * 4;

    // Load weights into smem ONCE per block (persistent blocks).
    for (int i = tid; i < LDIM * FDIM; i += NTHREADS) M1s[i] = g_M1[i];
    for (int i = tid; i < FDIM * LDIM; i += NTHREADS) W2s[i] = W2[i];
    float gm[3], bt[3];
    #pragma unroll
    for (int i = 0; i < 3; ++i) {
        gm[i] = gamma[lane + 32 * i];
        bt[i] = beta[lane + 32 * i];
    }
    __syncthreads();

    for (int tile = blockIdx.x; tile < ntiles; tile += gridDim.x) {
        // ---- Load X tile (64 x 96) transposed into Xs[k][r], float4 from gmem ----
        {
            const float4* xg4 = (const float4*)(x + (size_t)tile * (TILE_R * LDIM));
            #pragma unroll
            for (int j = 0; j < (TILE_R * LDIM / 4) / NTHREADS; ++j) {  // 3 iters
                int i4 = tid + j * NTHREADS;
                float4 v = xg4[i4];
                int e = i4 * 4;
                int r = e / LDIM;
                int c = e - r * LDIM;    // 96 % 4 == 0 -> never crosses row
                Xs[(c + 0) * PAD + r] = v.x;
                Xs[(c + 1) * PAD + r] = v.y;
                Xs[(c + 2) * PAD + r] = v.z;
                Xs[(c + 3) * PAD + r] = v.w;
            }
        }
        __syncthreads();

        // ---- GEMM1: H(64x192) = relu( X(64x96) @ M1(96x192) ) ----
        {
            float acc[4][6];
            #pragma unroll
            for (int ii = 0; ii < 4; ++ii)
                #pragma unroll
                for (int i = 0; i < 6; ++i) acc[ii][i] = 0.f;

            #pragma unroll 4
            for (int k = 0; k < LDIM; ++k) {
                float a0 = Xs[k * PAD + r0 + 0];   // warp-broadcast loads
                float a1 = Xs[k * PAD + r0 + 1];
                float a2 = Xs[k * PAD + r0 + 2];
                float a3 = Xs[k * PAD + r0 + 3];
                const float* mrow = &M1s[k * FDIM + lane];
                #pragma unroll
                for (int i = 0; i < 6; ++i) {
                    float b = mrow[32 * i];        // lane-stride 1: conflict-free
                    acc[0][i] += a0 * b;
                    acc[1][i] += a1 * b;
                    acc[2][i] += a2 * b;
                    acc[3][i] += a3 * b;
                }
            }
            #pragma unroll
            for (int ii = 0; ii < 4; ++ii)
                #pragma unroll
                for (int i = 0; i < 6; ++i)
                    Hs[(lane + 32 * i) * PAD + (r0 + ii)] = fmaxf(acc[ii][i], 0.f);
        }
        __syncthreads();

        // ---- GEMM2 + sigmoid + LayerNorm + x*lr ----
        {
            float acc[4][3];
            #pragma unroll
            for (int ii = 0; ii < 4; ++ii)
                #pragma unroll
                for (int i = 0; i < 3; ++i) acc[ii][i] = 0.f;

            #pragma unroll 4
            for (int k = 0; k < FDIM; ++k) {
                float a0 = Hs[k * PAD + r0 + 0];
                float a1 = Hs[k * PAD + r0 + 1];
                float a2 = Hs[k * PAD + r0 + 2];
                float a3 = Hs[k * PAD + r0 + 3];
                const float* wrow = &W2s[k * LDIM + lane];
                #pragma unroll
                for (int i = 0; i < 3; ++i) {
                    float b = wrow[32 * i];
                    acc[0][i] += a0 * b;
                    acc[1][i] += a1 * b;
                    acc[2][i] += a2 * b;
                    acc[3][i] += a3 * b;
                }
            }

            #pragma unroll
            for (int ii = 0; ii < 4; ++ii) {
                // sigmoid
                float v0 = 1.f / (1.f + expf(-acc[ii][0]));
                float v1 = 1.f / (1.f + expf(-acc[ii][1]));
                float v2 = 1.f / (1.f + expf(-acc[ii][2]));

                // LayerNorm over 96 (this warp holds the whole row: 32 lanes x 3)
                float s = v0 + v1 + v2;
                #pragma unroll
                for (int o = 16; o > 0; o >>= 1)
                    s += __shfl_xor_sync(0xffffffffu, s, o);
                float mu = s * (1.f / 96.f);

                float d0 = v0 - mu, d1 = v1 - mu, d2 = v2 - mu;
                float q = d0 * d0 + d1 * d1 + d2 * d2;
                #pragma unroll
                for (int o = 16; o > 0; o >>= 1)
                    q += __shfl_xor_sync(0xffffffffu, q, o);
                float inv = rsqrtf(q * (1.f / 96.f) + 1e-6f);

                size_t obase = ((size_t)tile * TILE_R + (size_t)(r0 + ii)) * LDIM;
                int r = r0 + ii;
                // out = x * ((lr - mu)*inv*gamma + beta); coalesced 128B stores
                out[obase + lane]      = Xs[(lane)      * PAD + r] * (d0 * inv * gm[0] + bt[0]);
                out[obase + lane + 32] = Xs[(lane + 32) * PAD + r] * (d1 * inv * gm[1] + bt[1]);
                out[obase + lane + 64] = Xs[(lane + 64) * PAD + r] * (d2 * inv * gm[2] + bt[2]);
            }
        }
        __syncthreads();   // protect Xs/Hs before next tile overwrites
    }
}

extern "C" void kernel_launch(void* const* d_in, const int* in_sizes, int n_in,
                              void* d_out, int out_size) {
    const float* x     = (const float*)d_in[0];
    const float* W1    = (const float*)d_in[1];
    const float* W2    = (const float*)d_in[2];
    const float* gamma = (const float*)d_in[3];
    const float* beta  = (const float*)d_in[4];
    float* out = (float*)d_out;

    int rows   = in_sizes[0] / LDIM;     // B*C = 786432
    int ntiles = rows / TILE_R;          // 12288

    // Fold DCT into W1 (tiny kernel, runs every launch -> deterministic)
    precompute_m1_kernel<<<LDIM, FDIM>>>(W1);

    const size_t smem_bytes =
        (size_t)(LDIM * FDIM + FDIM * LDIM + LDIM * PAD + FDIM * PAD) * sizeof(float); // 222,336 B
    cudaFuncSetAttribute(fused_dct_mlp_ln_kernel,
                         cudaFuncAttributeMaxDynamicSharedMemorySize,
                         (int)smem_bytes);

    int nsm = 148;
    cudaDeviceGetAttribute(&nsm, cudaDevAttrMultiProcessorCount, 0);
    int grid = nsm;
    if (grid > ntiles) grid = ntiles;

    fused_dct_mlp_ln_kernel<<<grid, NTHREADS, smem_bytes>>>(x, W2, gamma, beta, out, ntiles);
}